// round 1
// baseline (speedup 1.0000x reference)
#include <cuda_runtime.h>

#define RES 512
#define NC  32
#define TBL (RES * NC)          // 16384 floats per axis, transposed

// Transposed tables: [axis][row][comp] — 3 * 512 * 32 * 4B = 192KB static scratch.
__device__ float g_vt[3 * TBL];

// ---------------------------------------------------------------------------
// Prelude: transpose [C, R] -> [R, C] so one row's 32 components are one
// 128B line (coalesced gather). Tiny (192KB), cost ~1-2us.
// ---------------------------------------------------------------------------
__global__ void __launch_bounds__(256) transpose_tables(
    const float* __restrict__ vx,
    const float* __restrict__ vy,
    const float* __restrict__ vz)
{
    int g = blockIdx.x * blockDim.x + threadIdx.x;
    if (g >= 3 * TBL) return;
    int a   = g / TBL;
    int rem = g - a * TBL;
    int r   = rem >> 5;          // row 0..511
    int c   = rem & 31;          // comp 0..31
    const float* src = (a == 0) ? vx : (a == 1) ? vy : vz;
    g_vt[g] = src[c * RES + r];
}

// ---------------------------------------------------------------------------
// Per-axis 1D bilinear sample of 4 components (float4), transposed layout.
// ---------------------------------------------------------------------------
__device__ __forceinline__ float4 sample_axis(const float* __restrict__ base,
                                              float u, int cg)
{
    // map [-1,1] -> [0, R-1]:  ix = (u+1)*0.5*(R-1) = u*255.5 + 255.5
    float ix = fmaf(u, 255.5f, 255.5f);
    float fi = floorf(ix);
    float w  = ix - fi;
    int i0 = (int)fi;
    i0 = max(0, min(i0, RES - 1));
    int i1 = i0 + 1;
    if (i1 > RES - 1) { i1 = RES - 1; w = 0.0f; }   // zero-padding edge: weight->0

    const float4 v0 = *reinterpret_cast<const float4*>(base + i0 * NC + cg);
    const float4 v1 = *reinterpret_cast<const float4*>(base + i1 * NC + cg);

    float4 r;
    r.x = fmaf(w, v1.x - v0.x, v0.x);
    r.y = fmaf(w, v1.y - v0.y, v0.y);
    r.z = fmaf(w, v1.z - v0.z, v0.z);
    r.w = fmaf(w, v1.w - v0.w, v0.w);
    return r;
}

// ---------------------------------------------------------------------------
// Main kernel: warp = 4 points, lane l -> point (l>>3), comps ((l&7)*4 .. +3).
// Store per warp: 512B contiguous (fully coalesced STG.128).
// ---------------------------------------------------------------------------
__global__ void __launch_bounds__(256) cp_encode(
    const float* __restrict__ pos,
    float* __restrict__ out,
    int npts)
{
    int tid  = blockIdx.x * blockDim.x + threadIdx.x;
    int lane = threadIdx.x & 31;
    int n    = (tid >> 5) * 4 + (lane >> 3);   // point index
    if (n >= npts) return;
    int cg   = (lane & 7) << 2;                // component group start

    // positions: 8 lanes share a point -> broadcast sectors; streaming hint
    const float* p = pos + (size_t)n * 3;
    float x = __ldcs(p + 0);
    float y = __ldcs(p + 1);
    float z = __ldcs(p + 2);

    const float* bx = g_vt;
    const float* by = g_vt + TBL;
    const float* bz = g_vt + 2 * TBL;

    float4 fx = sample_axis(bx, x, cg);
    float4 fy = sample_axis(by, y, cg);
    float4 fz = sample_axis(bz, z, cg);

    float4 r;
    r.x = fx.x * fy.x * fz.x;
    r.y = fx.y * fy.y * fz.y;
    r.z = fx.z * fy.z * fz.z;
    r.w = fx.w * fy.w * fz.w;

    // streaming store (output never re-read)
    __stcs(reinterpret_cast<float4*>(out + (size_t)n * NC + cg), r);
}

// ---------------------------------------------------------------------------
// Launch
// ---------------------------------------------------------------------------
extern "C" void kernel_launch(void* const* d_in, const int* in_sizes, int n_in,
                              void* d_out, int out_size)
{
    const float* positions = (const float*)d_in[0];
    const float* vec_x     = (const float*)d_in[1];
    const float* vec_y     = (const float*)d_in[2];
    const float* vec_z     = (const float*)d_in[3];
    float* out = (float*)d_out;

    int npts = in_sizes[0] / 3;

    // 1) transpose tables into device scratch
    int telems = 3 * TBL;
    transpose_tables<<<(telems + 255) / 256, 256>>>(vec_x, vec_y, vec_z);

    // 2) encode: 8 threads per point
    long long total_threads = (long long)npts * 8;
    int blocks = (int)((total_threads + 255) / 256);
    cp_encode<<<blocks, 256>>>(positions, out, npts);
}

// round 2
// speedup vs baseline: 1.0004x; 1.0004x over previous
#include <cuda_runtime.h>

#define RES 512
#define NC  32
#define TBL (RES * NC)          // 16384 floats per axis, transposed

// Transposed tables: [axis][row][comp] — 3 * 512 * 32 * 4B = 192KB static scratch.
__device__ float g_vt[3 * TBL];

// ---------------------------------------------------------------------------
// Prelude: transpose [C, R] -> [R, C] so one row's 32 components are one
// 128B line (coalesced gather). Tiny (192KB), cost ~1-2us.
// ---------------------------------------------------------------------------
__global__ void __launch_bounds__(256) transpose_tables(
    const float* __restrict__ vx,
    const float* __restrict__ vy,
    const float* __restrict__ vz)
{
    int g = blockIdx.x * blockDim.x + threadIdx.x;
    if (g >= 3 * TBL) return;
    int a   = g / TBL;
    int rem = g - a * TBL;
    int r   = rem >> 5;          // row 0..511
    int c   = rem & 31;          // comp 0..31
    const float* src = (a == 0) ? vx : (a == 1) ? vy : vz;
    g_vt[g] = src[c * RES + r];
}

// ---------------------------------------------------------------------------
// Per-axis 1D bilinear sample of 4 components (float4), transposed layout.
// ---------------------------------------------------------------------------
__device__ __forceinline__ float4 sample_axis(const float* __restrict__ base,
                                              float u, int cg)
{
    // map [-1,1] -> [0, R-1]:  ix = (u+1)*0.5*(R-1) = u*255.5 + 255.5
    float ix = fmaf(u, 255.5f, 255.5f);
    float fi = floorf(ix);
    float w  = ix - fi;
    int i0 = (int)fi;
    i0 = max(0, min(i0, RES - 1));
    int i1 = i0 + 1;
    if (i1 > RES - 1) { i1 = RES - 1; w = 0.0f; }   // zero-padding edge: weight->0

    const float4 v0 = *reinterpret_cast<const float4*>(base + i0 * NC + cg);
    const float4 v1 = *reinterpret_cast<const float4*>(base + i1 * NC + cg);

    float4 r;
    r.x = fmaf(w, v1.x - v0.x, v0.x);
    r.y = fmaf(w, v1.y - v0.y, v0.y);
    r.z = fmaf(w, v1.z - v0.z, v0.z);
    r.w = fmaf(w, v1.w - v0.w, v0.w);
    return r;
}

// ---------------------------------------------------------------------------
// Main kernel: warp = 4 points, lane l -> point (l>>3), comps ((l&7)*4 .. +3).
// Store per warp: 512B contiguous (fully coalesced STG.128).
// ---------------------------------------------------------------------------
__global__ void __launch_bounds__(256) cp_encode(
    const float* __restrict__ pos,
    float* __restrict__ out,
    int npts)
{
    int tid  = blockIdx.x * blockDim.x + threadIdx.x;
    int lane = threadIdx.x & 31;
    int n    = (tid >> 5) * 4 + (lane >> 3);   // point index
    if (n >= npts) return;
    int cg   = (lane & 7) << 2;                // component group start

    // positions: 8 lanes share a point -> broadcast sectors; streaming hint
    const float* p = pos + (size_t)n * 3;
    float x = __ldcs(p + 0);
    float y = __ldcs(p + 1);
    float z = __ldcs(p + 2);

    const float* bx = g_vt;
    const float* by = g_vt + TBL;
    const float* bz = g_vt + 2 * TBL;

    float4 fx = sample_axis(bx, x, cg);
    float4 fy = sample_axis(by, y, cg);
    float4 fz = sample_axis(bz, z, cg);

    float4 r;
    r.x = fx.x * fy.x * fz.x;
    r.y = fx.y * fy.y * fz.y;
    r.z = fx.z * fy.z * fz.z;
    r.w = fx.w * fy.w * fz.w;

    // streaming store (output never re-read)
    __stcs(reinterpret_cast<float4*>(out + (size_t)n * NC + cg), r);
}

// ---------------------------------------------------------------------------
// Launch
// ---------------------------------------------------------------------------
extern "C" void kernel_launch(void* const* d_in, const int* in_sizes, int n_in,
                              void* d_out, int out_size)
{
    const float* positions = (const float*)d_in[0];
    const float* vec_x     = (const float*)d_in[1];
    const float* vec_y     = (const float*)d_in[2];
    const float* vec_z     = (const float*)d_in[3];
    float* out = (float*)d_out;

    int npts = in_sizes[0] / 3;

    // 1) transpose tables into device scratch
    int telems = 3 * TBL;
    transpose_tables<<<(telems + 255) / 256, 256>>>(vec_x, vec_y, vec_z);

    // 2) encode: 8 threads per point
    long long total_threads = (long long)npts * 8;
    int blocks = (int)((total_threads + 255) / 256);
    cp_encode<<<blocks, 256>>>(positions, out, npts);
}

// round 3
// speedup vs baseline: 1.0433x; 1.0430x over previous
#include <cuda_runtime.h>

#define RES 512
#define NC  32
#define TBL (RES * NC)          // 16384 floats per axis, transposed

// Transposed tables: [axis][row][comp] — 3 * 512 * 32 * 4B = 192KB static scratch.
__device__ float g_vt[3 * TBL];

// ---------------------------------------------------------------------------
// Prelude: transpose [C, R] -> [R, C] so one row's 32 components are one
// 128B line (coalesced gather).
// ---------------------------------------------------------------------------
__global__ void __launch_bounds__(256) transpose_tables(
    const float* __restrict__ vx,
    const float* __restrict__ vy,
    const float* __restrict__ vz)
{
    int g = blockIdx.x * blockDim.x + threadIdx.x;
    if (g >= 3 * TBL) return;
    int a   = g / TBL;
    int rem = g - a * TBL;
    int r   = rem >> 5;          // row 0..511
    int c   = rem & 31;          // comp 0..31
    const float* src = (a == 0) ? vx : (a == 1) ? vy : vz;
    g_vt[g] = src[c * RES + r];
}

// ---------------------------------------------------------------------------
// Index/weight prep. u in [-1,1] -> ix in [0, 511]; trunc == floor here.
// i0 == 511 only when ix == 511.0 exactly, where w == 0, so clamping i1
// to 511 reproduces zero-padding semantics with no extra branch.
// ---------------------------------------------------------------------------
struct Samp { int o0, o1; float w; };

__device__ __forceinline__ Samp prep(float u, int cg)
{
    float ix = fmaf(u, 255.5f, 255.5f);
    int   i0 = (int)ix;                       // floor (ix >= 0)
    i0 = min(i0, RES - 1);                    // safety for u == 1.0
    Samp s;
    s.w  = ix - (float)i0;
    s.o0 = i0 * NC + cg;
    s.o1 = min(i0 + 1, RES - 1) * NC + cg;
    return s;
}

__device__ __forceinline__ float4 lerp4(float4 a, float4 b, float w)
{
    float4 r;
    r.x = fmaf(w, b.x - a.x, a.x);
    r.y = fmaf(w, b.y - a.y, a.y);
    r.z = fmaf(w, b.z - a.z, a.z);
    r.w = fmaf(w, b.w - a.w, a.w);
    return r;
}

__device__ __forceinline__ float4 ld4(const float* __restrict__ p)
{
    return *reinterpret_cast<const float4*>(p);
}

// ---------------------------------------------------------------------------
// Main kernel: warp = 8 points; thread handles points n0 and n0+4.
// lane l -> point offset (l>>3), comps ((l&7)*4 .. +3).
// 12 independent LDG.128 per thread batched for MLP.
// ---------------------------------------------------------------------------
__global__ void __launch_bounds__(256) cp_encode(
    const float* __restrict__ pos,
    float* __restrict__ out,
    int npts)
{
    int warp = (blockIdx.x * blockDim.x + threadIdx.x) >> 5;
    int lane = threadIdx.x & 31;
    int n0   = warp * 8 + (lane >> 3);
    int n1   = n0 + 4;
    int cg   = (lane & 7) << 2;

    if (n0 >= npts) return;
    bool has1 = (n1 < npts);

    const float* p0 = pos + (size_t)n0 * 3;
    float x0 = __ldcs(p0 + 0);
    float y0 = __ldcs(p0 + 1);
    float z0 = __ldcs(p0 + 2);

    const float* p1 = pos + (size_t)(has1 ? n1 : n0) * 3;
    float x1 = __ldcs(p1 + 0);
    float y1 = __ldcs(p1 + 1);
    float z1 = __ldcs(p1 + 2);

    const float* bx = g_vt;
    const float* by = g_vt + TBL;
    const float* bz = g_vt + 2 * TBL;

    Samp sx0 = prep(x0, cg), sy0 = prep(y0, cg), sz0 = prep(z0, cg);
    Samp sx1 = prep(x1, cg), sy1 = prep(y1, cg), sz1 = prep(z1, cg);

    // ---- batch all 12 table loads (independent -> high MLP) ----
    float4 ax0 = ld4(bx + sx0.o0), bx0 = ld4(bx + sx0.o1);
    float4 ay0 = ld4(by + sy0.o0), by0 = ld4(by + sy0.o1);
    float4 az0 = ld4(bz + sz0.o0), bz0 = ld4(bz + sz0.o1);
    float4 ax1 = ld4(bx + sx1.o0), bx1 = ld4(bx + sx1.o1);
    float4 ay1 = ld4(by + sy1.o0), by1 = ld4(by + sy1.o1);
    float4 az1 = ld4(bz + sz1.o0), bz1 = ld4(bz + sz1.o1);

    // ---- interpolate + product ----
    float4 fx0 = lerp4(ax0, bx0, sx0.w);
    float4 fy0 = lerp4(ay0, by0, sy0.w);
    float4 fz0 = lerp4(az0, bz0, sz0.w);
    float4 fx1 = lerp4(ax1, bx1, sx1.w);
    float4 fy1 = lerp4(ay1, by1, sy1.w);
    float4 fz1 = lerp4(az1, bz1, sz1.w);

    float4 r0, r1;
    r0.x = fx0.x * fy0.x * fz0.x;
    r0.y = fx0.y * fy0.y * fz0.y;
    r0.z = fx0.z * fy0.z * fz0.z;
    r0.w = fx0.w * fy0.w * fz0.w;
    r1.x = fx1.x * fy1.x * fz1.x;
    r1.y = fx1.y * fy1.y * fz1.y;
    r1.z = fx1.z * fy1.z * fz1.z;
    r1.w = fx1.w * fy1.w * fz1.w;

    __stcs(reinterpret_cast<float4*>(out + (size_t)n0 * NC + cg), r0);
    if (has1)
        __stcs(reinterpret_cast<float4*>(out + (size_t)n1 * NC + cg), r1);
}

// ---------------------------------------------------------------------------
// Launch
// ---------------------------------------------------------------------------
extern "C" void kernel_launch(void* const* d_in, const int* in_sizes, int n_in,
                              void* d_out, int out_size)
{
    const float* positions = (const float*)d_in[0];
    const float* vec_x     = (const float*)d_in[1];
    const float* vec_y     = (const float*)d_in[2];
    const float* vec_z     = (const float*)d_in[3];
    float* out = (float*)d_out;

    int npts = in_sizes[0] / 3;

    int telems = 3 * TBL;
    transpose_tables<<<(telems + 255) / 256, 256>>>(vec_x, vec_y, vec_z);

    // 4 threads per point (8 points per warp, 2 per thread)
    long long total_threads = ((long long)npts + 7) / 8 * 32;
    int blocks = (int)((total_threads + 255) / 256);
    cp_encode<<<blocks, 256>>>(positions, out, npts);
}

// round 4
// speedup vs baseline: 1.2275x; 1.1765x over previous
#include <cuda_runtime.h>
#include <cuda_fp16.h>

#define RES 512
#define NC  32
#define TBL (RES * NC)          // 16384 entries per axis

// Paired tables: entry (axis, r, c) = half2( v[c][r], v[c][r+1] ).
// 3 * 512 * 32 * 4B = 192KB -> L1-resident. Stored as uint4 for 16B alignment.
// One 128B row read per axis delivers BOTH interpolation neighbors for all 32 comps.
__device__ uint4 g_pair4[3 * RES * (NC / 4)];   // 3*512*8 uint4

// ---------------------------------------------------------------------------
// Prelude: transpose + pair-pack [C,R] fp32 -> [R, C] half2(v_r, v_{r+1}).
// r = 511 pairs with 0; unreachable anyway since w == 0 there.
// ---------------------------------------------------------------------------
__global__ void __launch_bounds__(256) pack_tables(
    const float* __restrict__ vx,
    const float* __restrict__ vy,
    const float* __restrict__ vz)
{
    int g = blockIdx.x * blockDim.x + threadIdx.x;
    if (g >= 3 * TBL) return;
    int a   = g / TBL;
    int rem = g - a * TBL;
    int r   = rem >> 5;          // row  0..511
    int c   = rem & 31;          // comp 0..31
    const float* src = (a == 0) ? vx : (a == 1) ? vy : vz;
    float v0 = src[c * RES + r];
    float v1 = (r < RES - 1) ? src[c * RES + r + 1] : 0.0f;
    reinterpret_cast<__half2*>(g_pair4)[g] = __floats2half2_rn(v0, v1);
}

// ---------------------------------------------------------------------------
// Index/weight prep. u in [-1,1] -> ix in [0,511]; trunc == floor.
// At i0 == 511 (only when ix == 511.0) w == 0, so the pair's second half
// is never weighted in -> matches zero-padding semantics.
// ---------------------------------------------------------------------------
struct Samp { int off; float w; };

__device__ __forceinline__ Samp prep(float u, int q)
{
    float ix = fmaf(u, 255.5f, 255.5f);
    int   i0 = min((int)ix, RES - 1);
    Samp s;
    s.w   = ix - (float)i0;
    s.off = i0 * (NC / 4) + q;          // uint4 index within axis table
    return s;
}

// Unpack 4 half2 pairs and lerp in fp32: f = v0 + w*(v1 - v0)
__device__ __forceinline__ float4 lerp_pair(uint4 p, float w)
{
    float2 a = __half22float2(*reinterpret_cast<__half2*>(&p.x));
    float2 b = __half22float2(*reinterpret_cast<__half2*>(&p.y));
    float2 c = __half22float2(*reinterpret_cast<__half2*>(&p.z));
    float2 d = __half22float2(*reinterpret_cast<__half2*>(&p.w));
    float4 r;
    r.x = fmaf(w, a.y - a.x, a.x);
    r.y = fmaf(w, b.y - b.x, b.x);
    r.z = fmaf(w, c.y - c.x, c.x);
    r.w = fmaf(w, d.y - d.x, d.x);
    return r;
}

// ---------------------------------------------------------------------------
// Main kernel: warp = 8 points; thread handles points n0 and n0+4.
// lane l -> point offset (l>>3), comps ((l&7)*4 .. +3) == uint4 slot (l&7).
// 6 independent LDG.128 per thread (one per point-axis), batched for MLP.
// ---------------------------------------------------------------------------
__global__ void __launch_bounds__(256) cp_encode(
    const float* __restrict__ pos,
    float* __restrict__ out,
    int npts)
{
    int warp = (blockIdx.x * blockDim.x + threadIdx.x) >> 5;
    int lane = threadIdx.x & 31;
    int n0   = warp * 8 + (lane >> 3);
    int n1   = n0 + 4;
    int q    = lane & 7;                 // uint4 slot (4 comps)

    if (n0 >= npts) return;
    bool has1 = (n1 < npts);

    const float* p0 = pos + (size_t)n0 * 3;
    float x0 = __ldcs(p0 + 0);
    float y0 = __ldcs(p0 + 1);
    float z0 = __ldcs(p0 + 2);

    const float* p1 = pos + (size_t)(has1 ? n1 : n0) * 3;
    float x1 = __ldcs(p1 + 0);
    float y1 = __ldcs(p1 + 1);
    float z1 = __ldcs(p1 + 2);

    const uint4* bx = g_pair4;
    const uint4* by = g_pair4 + RES * (NC / 4);
    const uint4* bz = g_pair4 + 2 * RES * (NC / 4);

    Samp sx0 = prep(x0, q), sy0 = prep(y0, q), sz0 = prep(z0, q);
    Samp sx1 = prep(x1, q), sy1 = prep(y1, q), sz1 = prep(z1, q);

    // ---- batch all 6 table loads (independent -> high MLP) ----
    uint4 hx0 = bx[sx0.off];
    uint4 hy0 = by[sy0.off];
    uint4 hz0 = bz[sz0.off];
    uint4 hx1 = bx[sx1.off];
    uint4 hy1 = by[sy1.off];
    uint4 hz1 = bz[sz1.off];

    // ---- interpolate (fp32) + product ----
    float4 fx0 = lerp_pair(hx0, sx0.w);
    float4 fy0 = lerp_pair(hy0, sy0.w);
    float4 fz0 = lerp_pair(hz0, sz0.w);
    float4 fx1 = lerp_pair(hx1, sx1.w);
    float4 fy1 = lerp_pair(hy1, sy1.w);
    float4 fz1 = lerp_pair(hz1, sz1.w);

    float4 r0, r1;
    r0.x = fx0.x * fy0.x * fz0.x;
    r0.y = fx0.y * fy0.y * fz0.y;
    r0.z = fx0.z * fy0.z * fz0.z;
    r0.w = fx0.w * fy0.w * fz0.w;
    r1.x = fx1.x * fy1.x * fz1.x;
    r1.y = fx1.y * fy1.y * fz1.y;
    r1.z = fx1.z * fy1.z * fz1.z;
    r1.w = fx1.w * fy1.w * fz1.w;

    __stcs(reinterpret_cast<float4*>(out + (size_t)n0 * NC + (q << 2)), r0);
    if (has1)
        __stcs(reinterpret_cast<float4*>(out + (size_t)n1 * NC + (q << 2)), r1);
}

// ---------------------------------------------------------------------------
// Launch
// ---------------------------------------------------------------------------
extern "C" void kernel_launch(void* const* d_in, const int* in_sizes, int n_in,
                              void* d_out, int out_size)
{
    const float* positions = (const float*)d_in[0];
    const float* vec_x     = (const float*)d_in[1];
    const float* vec_y     = (const float*)d_in[2];
    const float* vec_z     = (const float*)d_in[3];
    float* out = (float*)d_out;

    int npts = in_sizes[0] / 3;

    int telems = 3 * TBL;
    pack_tables<<<(telems + 255) / 256, 256>>>(vec_x, vec_y, vec_z);

    // 4 threads per point (8 points per warp, 2 per thread)
    long long total_threads = ((long long)npts + 7) / 8 * 32;
    int blocks = (int)((total_threads + 255) / 256);
    cp_encode<<<blocks, 256>>>(positions, out, npts);
}

// round 5
// speedup vs baseline: 1.2965x; 1.0562x over previous
#include <cuda_runtime.h>
#include <cuda_fp16.h>

#define RES 512
#define NC  32
#define TBL (RES * NC)          // 16384 entries per axis

// Paired tables: entry (axis, r, c) = half2( v[c][r], v[c][r+1] ).
// 3 * 512 * 32 * 4B = 192KB -> L1-resident. Stored as uint4 rows.
__device__ uint4 g_pair4[3 * RES * (NC / 4)];

// ---------------------------------------------------------------------------
// Prelude: transpose + pair-pack [C,R] fp32 -> [R,C] half2(v_r, v_{r+1}).
// ---------------------------------------------------------------------------
__global__ void __launch_bounds__(256) pack_tables(
    const float* __restrict__ vx,
    const float* __restrict__ vy,
    const float* __restrict__ vz)
{
    int g = blockIdx.x * blockDim.x + threadIdx.x;
    if (g >= 3 * TBL) return;
    int a   = g / TBL;
    int rem = g - a * TBL;
    int r   = rem >> 5;
    int c   = rem & 31;
    const float* src = (a == 0) ? vx : (a == 1) ? vy : vz;
    float v0 = src[c * RES + r];
    float v1 = (r < RES - 1) ? src[c * RES + r + 1] : 0.0f;
    reinterpret_cast<__half2*>(g_pair4)[g] = __floats2half2_rn(v0, v1);
}

// ---------------------------------------------------------------------------
struct Samp { int off; float w; };

__device__ __forceinline__ Samp prep(float u, int q)
{
    float ix = fmaf(u, 255.5f, 255.5f);
    int   i0 = min((int)ix, RES - 1);
    Samp s;
    s.w   = ix - (float)i0;
    s.off = i0 * (NC / 4) + q;
    return s;
}

__device__ __forceinline__ float4 lerp_pair(uint4 p, float w)
{
    float2 a = __half22float2(*reinterpret_cast<__half2*>(&p.x));
    float2 b = __half22float2(*reinterpret_cast<__half2*>(&p.y));
    float2 c = __half22float2(*reinterpret_cast<__half2*>(&p.z));
    float2 d = __half22float2(*reinterpret_cast<__half2*>(&p.w));
    float4 r;
    r.x = fmaf(w, a.y - a.x, a.x);
    r.y = fmaf(w, b.y - b.x, b.x);
    r.z = fmaf(w, c.y - c.x, c.x);
    r.w = fmaf(w, d.y - d.x, d.x);
    return r;
}

// ---------------------------------------------------------------------------
// Persistent kernel: warp owns a strided strip of point-groups of 8.
// Within a warp: lane l -> point offset (l>>3), uint4 slot (l&7).
// Each thread handles 2 points per iteration (n, n+4).
// Position loads for the next iteration are rotated ahead of the stores.
// ---------------------------------------------------------------------------
__global__ void __launch_bounds__(256) cp_encode(
    const float* __restrict__ pos,
    float* __restrict__ out,
    int npts, int stride)        // stride = total points per full-grid iteration
{
    int warp = (blockIdx.x * blockDim.x + threadIdx.x) >> 5;
    int lane = threadIdx.x & 31;
    int q    = lane & 7;

    const uint4* bx = g_pair4;
    const uint4* by = g_pair4 + RES * (NC / 4);
    const uint4* bz = g_pair4 + 2 * RES * (NC / 4);

    int n0 = warp * 8 + (lane >> 3);
    if (n0 >= npts) return;

    // initial position load
    const float* p0 = pos + (size_t)n0 * 3;
    float x0 = __ldcs(p0 + 0), y0 = __ldcs(p0 + 1), z0 = __ldcs(p0 + 2);
    int   n1c = min(n0 + 4, npts - 1);
    const float* p1 = pos + (size_t)n1c * 3;
    float x1 = __ldcs(p1 + 0), y1 = __ldcs(p1 + 1), z1 = __ldcs(p1 + 2);

    while (true) {
        bool has1 = (n0 + 4 < npts);

        Samp sx0 = prep(x0, q), sy0 = prep(y0, q), sz0 = prep(z0, q);
        Samp sx1 = prep(x1, q), sy1 = prep(y1, q), sz1 = prep(z1, q);

        // ---- batch all 6 independent table loads ----
        uint4 hx0 = bx[sx0.off];
        uint4 hy0 = by[sy0.off];
        uint4 hz0 = bz[sz0.off];
        uint4 hx1 = bx[sx1.off];
        uint4 hy1 = by[sy1.off];
        uint4 hz1 = bz[sz1.off];

        // ---- rotate in next iteration's positions (hide pos latency) ----
        int nn = n0 + stride;
        bool more = (nn < npts);
        if (more) {
            const float* q0 = pos + (size_t)nn * 3;
            int nn1 = min(nn + 4, npts - 1);
            const float* q1 = pos + (size_t)nn1 * 3;
            x0 = __ldcs(q0 + 0); y0 = __ldcs(q0 + 1); z0 = __ldcs(q0 + 2);
            x1 = __ldcs(q1 + 0); y1 = __ldcs(q1 + 1); z1 = __ldcs(q1 + 2);
        }

        // ---- interpolate + product ----
        float4 fx0 = lerp_pair(hx0, sx0.w);
        float4 fy0 = lerp_pair(hy0, sy0.w);
        float4 fz0 = lerp_pair(hz0, sz0.w);
        float4 fx1 = lerp_pair(hx1, sx1.w);
        float4 fy1 = lerp_pair(hy1, sy1.w);
        float4 fz1 = lerp_pair(hz1, sz1.w);

        float4 r0, r1;
        r0.x = fx0.x * fy0.x * fz0.x;
        r0.y = fx0.y * fy0.y * fz0.y;
        r0.z = fx0.z * fy0.z * fz0.z;
        r0.w = fx0.w * fy0.w * fz0.w;
        r1.x = fx1.x * fy1.x * fz1.x;
        r1.y = fx1.y * fy1.y * fz1.y;
        r1.z = fx1.z * fy1.z * fz1.z;
        r1.w = fx1.w * fy1.w * fz1.w;

        __stcs(reinterpret_cast<float4*>(out + (size_t)n0 * NC + (q << 2)), r0);
        if (has1)
            __stcs(reinterpret_cast<float4*>(out + (size_t)(n0 + 4) * NC + (q << 2)), r1);

        if (!more) break;
        n0 = nn;
    }
}

// ---------------------------------------------------------------------------
extern "C" void kernel_launch(void* const* d_in, const int* in_sizes, int n_in,
                              void* d_out, int out_size)
{
    const float* positions = (const float*)d_in[0];
    const float* vec_x     = (const float*)d_in[1];
    const float* vec_y     = (const float*)d_in[2];
    const float* vec_z     = (const float*)d_in[3];
    float* out = (float*)d_out;

    int npts = in_sizes[0] / 3;

    int telems = 3 * TBL;
    pack_tables<<<(telems + 255) / 256, 256>>>(vec_x, vec_y, vec_z);

    // persistent grid: 6 blocks/SM * 148 SMs, 8 warps each; 8 pts per warp-iter
    const int blocks = 148 * 6;
    const int threads = 256;
    int warps = blocks * (threads / 32);
    int stride = warps * 8;     // points consumed per full-grid iteration

    cp_encode<<<blocks, threads>>>(positions, out, npts, stride);
}